// round 14
// baseline (speedup 1.0000x reference)
#include <cuda_runtime.h>
#include <math.h>

// Shape fixed by reference: x,y = [16, 3, 512, 512] f32
#define BATCH   16
#define HDIM    512
#define WDIM    512
#define RSTRIP  16                    // output rows per block
#define STRIPS  (HDIM / RSTRIP)       // 32
#define CSPLIT  2                     // column tiles per image
#define CTILE   (WDIM / CSPLIT)       // 256
#define NBLOCKS (BATCH * STRIPS * CSPLIT)  // 1024
#define THREADS 64                    // one float4 column per thread (2 warps)
#define ROWSIN  (RSTRIP + 6)          // 22 streamed rows
#define ITERS   (ROWSIN / 2)          // 11 (2 rows per iteration)
#define EPSV    1e-6f

__device__ float        g_partials[NBLOCKS];
__device__ unsigned int g_count;     // zero-init at load; reset by last block

__global__ __launch_bounds__(THREADS, 8) void charb_kernel(
    const float* __restrict__ x, const float* __restrict__ y,
    float* __restrict__ out)
{
    __shared__ float drow[2][2][264]; // [bufset][row-of-pair]: 4 halo + 256 + 4 halo
    __shared__ float hl[ROWSIN][4];   // left seam diff per stream row
    __shared__ float hr[ROWSIN][4];   // right seam diff per stream row
    __shared__ float warpsum[2];
    __shared__ bool  isLast;

    const int tid  = threadIdx.x;
    const int lane = tid & 31;
    const int c0   = tid << 2;        // this thread's 4 local columns

    const int blk = blockIdx.x;
    const int b   = blk >> 6;                 // batch
    const int s   = (blk >> 1) & 31;          // strip
    const int ct  = blk & 1;                  // column tile (fastest-varying)
    const int h0  = s * RSTRIP;
    const int cb  = ct * CTILE;
    const bool rev = (s & 1);                 // serpentine rows
    const int rbase = rev ? (h0 + RSTRIP + 2) : (h0 - 3);
    const int rstep = rev ? -1 : 1;

    const size_t plane = (size_t)HDIM * WDIM;
    const float* xi = x + (size_t)b * 3 * plane;
    const float* yi = y + (size_t)b * 3 * plane;

    // ---- prologue: stage seam diffs (left: cols cb-4..cb-1, right: cb+256..cb+259)
    {
        const bool left  = (tid < ROWSIN);                    // threads 0..21
        const bool right = (tid >= 32 && tid < 32 + ROWSIN);  // threads 32..53
        if (left || right) {
            const int rr   = left ? tid : (tid - 32);
            const int gcol = left ? (cb - 4) : (cb + CTILE);
            const int r    = rbase + rstep * rr;
            float4 v = make_float4(0.f, 0.f, 0.f, 0.f);
            if (gcol >= 0 && gcol < WDIM && r >= 0 && r < HDIM) {
                const float* xp = xi + (size_t)r * WDIM + gcol;
                const float* yp = yi + (size_t)r * WDIM + gcol;
                const float4 a0 = *(const float4*)(xp);
                const float4 a1 = *(const float4*)(xp + plane);
                const float4 a2 = *(const float4*)(xp + 2 * plane);
                const float4 q0 = *(const float4*)(yp);
                const float4 q1 = *(const float4*)(yp + plane);
                const float4 q2 = *(const float4*)(yp + 2 * plane);
                v.x = (a0.x - q0.x) + (a1.x - q1.x) + (a2.x - q2.x);
                v.y = (a0.y - q0.y) + (a1.y - q1.y) + (a2.y - q2.y);
                v.z = (a0.z - q0.z) + (a1.z - q1.z) + (a2.z - q2.z);
                v.w = (a0.w - q0.w) + (a1.w - q1.w) + (a2.w - q2.w);
            }
            if (left) *(float4*)hl[rr] = v;
            else      *(float4*)hr[rr] = v;
        }
    }

    const float* xb = xi + cb + c0;
    const float* yb = yi + cb + c0;

    const float4 z4 = make_float4(0.f, 0.f, 0.f, 0.f);
    float4 Aa0 = z4, Aa1 = z4, Aa2 = z4, Aq0 = z4, Aq1 = z4, Aq2 = z4;
    float4 Ba0 = z4, Ba1 = z4, Ba2 = z4, Bq0 = z4, Bq1 = z4, Bq2 = z4;

    {   // prologue: load stream rows 0 and 1
        const int rA = rbase;
        if (rA >= 0 && rA < HDIM) {
            const float* xp = xb + (size_t)rA * WDIM;
            const float* yp = yb + (size_t)rA * WDIM;
            Aa0 = *(const float4*)(xp);
            Aa1 = *(const float4*)(xp + plane);
            Aa2 = *(const float4*)(xp + 2 * plane);
            Aq0 = *(const float4*)(yp);
            Aq1 = *(const float4*)(yp + plane);
            Aq2 = *(const float4*)(yp + 2 * plane);
        }
        const int rB = rbase + rstep;
        if (rB >= 0 && rB < HDIM) {
            const float* xp = xb + (size_t)rB * WDIM;
            const float* yp = yb + (size_t)rB * WDIM;
            Ba0 = *(const float4*)(xp);
            Ba1 = *(const float4*)(xp + plane);
            Ba2 = *(const float4*)(xp + 2 * plane);
            Bq0 = *(const float4*)(yp);
            Bq1 = *(const float4*)(yp + plane);
            Bq2 = *(const float4*)(yp + 2 * plane);
        }
    }
    __syncthreads();   // hl/hr staged

    // vertical register ring (6 previous hsum rows) + running 7-row sum
    float4 r0 = z4, r1 = z4, r2 = z4, r3 = z4, r4 = z4, r5 = z4;
    float4 vs = z4;
    float  acc = 0.f;

    #pragma unroll 1
    for (int it = 0; it < ITERS; ++it) {
        const int i0 = 2 * it;
        const int bs = it & 1;

        // channel-summed diffs for rows i0, i0+1 -> smem buffer set bs
        {
            float4 d;
            d.x = (Aa0.x - Aq0.x) + (Aa1.x - Aq1.x) + (Aa2.x - Aq2.x);
            d.y = (Aa0.y - Aq0.y) + (Aa1.y - Aq1.y) + (Aa2.y - Aq2.y);
            d.z = (Aa0.z - Aq0.z) + (Aa1.z - Aq1.z) + (Aa2.z - Aq2.z);
            d.w = (Aa0.w - Aq0.w) + (Aa1.w - Aq1.w) + (Aa2.w - Aq2.w);
            *(float4*)&drow[bs][0][4 + c0] = d;
        }
        {
            float4 d;
            d.x = (Ba0.x - Bq0.x) + (Ba1.x - Bq1.x) + (Ba2.x - Bq2.x);
            d.y = (Ba0.y - Bq0.y) + (Ba1.y - Bq1.y) + (Ba2.y - Bq2.y);
            d.z = (Ba0.z - Bq0.z) + (Ba1.z - Bq1.z) + (Ba2.z - Bq2.z);
            d.w = (Ba0.w - Bq0.w) + (Ba1.w - Bq1.w) + (Ba2.w - Bq2.w);
            *(float4*)&drow[bs][1][4 + c0] = d;
        }
        // seam splice (smem -> smem, no registers held across rows)
        if (tid == 0) {
            *(float4*)&drow[bs][0][0] = *(const float4*)hl[i0];
            *(float4*)&drow[bs][1][0] = *(const float4*)hl[i0 + 1];
        }
        if (tid == THREADS - 1) {
            *(float4*)&drow[bs][0][260] = *(const float4*)hr[i0];
            *(float4*)&drow[bs][1][260] = *(const float4*)hr[i0 + 1];
        }

        // prefetch rows i0+2, i0+3 (12 independent LDG.128 in flight)
        {
            const int niA = i0 + 2;
            const int nrA = rbase + rstep * niA;
            const bool vA = (niA < ROWSIN) && (nrA >= 0) && (nrA < HDIM);
            Aa0 = z4; Aa1 = z4; Aa2 = z4; Aq0 = z4; Aq1 = z4; Aq2 = z4;
            if (vA) {
                const float* xp = xb + (size_t)nrA * WDIM;
                const float* yp = yb + (size_t)nrA * WDIM;
                Aa0 = *(const float4*)(xp);
                Aa1 = *(const float4*)(xp + plane);
                Aa2 = *(const float4*)(xp + 2 * plane);
                Aq0 = *(const float4*)(yp);
                Aq1 = *(const float4*)(yp + plane);
                Aq2 = *(const float4*)(yp + 2 * plane);
            }
            const int niB = i0 + 3;
            const int nrB = rbase + rstep * niB;
            const bool vB = (niB < ROWSIN) && (nrB >= 0) && (nrB < HDIM);
            Ba0 = z4; Ba1 = z4; Ba2 = z4; Bq0 = z4; Bq1 = z4; Bq2 = z4;
            if (vB) {
                const float* xp = xb + (size_t)nrB * WDIM;
                const float* yp = yb + (size_t)nrB * WDIM;
                Ba0 = *(const float4*)(xp);
                Ba1 = *(const float4*)(xp + plane);
                Ba2 = *(const float4*)(xp + 2 * plane);
                Bq0 = *(const float4*)(yp);
                Bq1 = *(const float4*)(yp + plane);
                Bq2 = *(const float4*)(yp + 2 * plane);
            }
        }

        __syncthreads();   // publishes bufset bs (2 warps only); WAR gate

        // ---- row i0: horizontal 7-tap + vertical update ----
        {
            float f[12];
            *(float4*)&f[0] = *(const float4*)&drow[bs][0][c0];
            *(float4*)&f[4] = *(const float4*)&drow[bs][0][c0 + 4];
            *(float4*)&f[8] = *(const float4*)&drow[bs][0][c0 + 8];
            float4 s4;
            s4.x = ((f[1] + f[2]) + (f[3] + f[4])) + ((f[5] + f[6]) + f[7]);
            s4.y = s4.x - f[1] + f[8];
            s4.z = s4.y - f[2] + f[9];
            s4.w = s4.z - f[3] + f[10];

            vs.x += s4.x; vs.y += s4.y; vs.z += s4.z; vs.w += s4.w;
            if (i0 >= 6) {
                const float inv = 1.f / 49.f;
                const float v0 = vs.x * inv, v1 = vs.y * inv;
                const float v2 = vs.z * inv, v3 = vs.w * inv;
                acc += (sqrtf(v0 * v0 + EPSV) + sqrtf(v1 * v1 + EPSV))
                     + (sqrtf(v2 * v2 + EPSV) + sqrtf(v3 * v3 + EPSV));
                vs.x -= r0.x; vs.y -= r0.y; vs.z -= r0.z; vs.w -= r0.w;
            }
            r0 = r1; r1 = r2; r2 = r3; r3 = r4; r4 = r5; r5 = s4;
        }

        // ---- row i0+1 ----
        {
            float f[12];
            *(float4*)&f[0] = *(const float4*)&drow[bs][1][c0];
            *(float4*)&f[4] = *(const float4*)&drow[bs][1][c0 + 4];
            *(float4*)&f[8] = *(const float4*)&drow[bs][1][c0 + 8];
            float4 s4;
            s4.x = ((f[1] + f[2]) + (f[3] + f[4])) + ((f[5] + f[6]) + f[7]);
            s4.y = s4.x - f[1] + f[8];
            s4.z = s4.y - f[2] + f[9];
            s4.w = s4.z - f[3] + f[10];

            vs.x += s4.x; vs.y += s4.y; vs.z += s4.z; vs.w += s4.w;
            if (i0 + 1 >= 6) {
                const float inv = 1.f / 49.f;
                const float v0 = vs.x * inv, v1 = vs.y * inv;
                const float v2 = vs.z * inv, v3 = vs.w * inv;
                acc += (sqrtf(v0 * v0 + EPSV) + sqrtf(v1 * v1 + EPSV))
                     + (sqrtf(v2 * v2 + EPSV) + sqrtf(v3 * v3 + EPSV));
                vs.x -= r0.x; vs.y -= r0.y; vs.z -= r0.z; vs.w -= r0.w;
            }
            r0 = r1; r1 = r2; r2 = r3; r3 = r4; r4 = r5; r5 = s4;
        }
    }

    // block reduction (2 warps)
    #pragma unroll
    for (int off = 16; off; off >>= 1) acc += __shfl_xor_sync(0xffffffffu, acc, off);
    if (lane == 0) warpsum[tid >> 5] = acc;
    __syncthreads();
    if (tid == 0) {
        g_partials[blk] = warpsum[0] + warpsum[1];
        __threadfence();
        const unsigned int t = atomicAdd(&g_count, 1u);
        isLast = (t == NBLOCKS - 1);
    }
    __syncthreads();

    // last-arriving block folds the 1024 partials -> scalar (deterministic order)
    if (isLast) {
        __threadfence();
        float v = 0.f;
        #pragma unroll
        for (int k = 0; k < NBLOCKS / THREADS; ++k)
            v += g_partials[tid + k * THREADS];
        #pragma unroll
        for (int off = 16; off; off >>= 1) v += __shfl_xor_sync(0xffffffffu, v, off);
        if (lane == 0) warpsum[tid >> 5] = v;
        __syncthreads();
        if (tid == 0) {
            out[0]  = (warpsum[0] + warpsum[1]) / (float)((size_t)BATCH * HDIM * WDIM);
            g_count = 0u;
        }
    }
}

extern "C" void kernel_launch(void* const* d_in, const int* in_sizes, int n_in,
                              void* d_out, int out_size)
{
    (void)in_sizes; (void)n_in; (void)out_size;
    const float* x = (const float*)d_in[0];
    const float* y = (const float*)d_in[1];
    float* out = (float*)d_out;

    charb_kernel<<<NBLOCKS, THREADS>>>(x, y, out);
}